// round 1
// baseline (speedup 1.0000x reference)
#include <cuda_runtime.h>

// WindowAttentionGlobal: per-window fused
//   kv = x @ W_kv + b_kv          -> k,v [H][N][hd]
//   attn = softmax(q*scale @ k^T + bias)
//   o = attn @ v ; out = o @ W_proj + b_proj
//
// Shapes: B_=4096 windows, N=49 tokens, DIM=128, HEADS=4, hd=32.
// One CTA per window, 256 threads.

#define NWIN   49
#define DIMC   128
#define HEADS  4
#define HD     32
#define SCALE  0.17677669529663689f   // 32^-0.5

// smem layout (floats):
//   xs/os : 49*132 = 6468   (x tile, later reused as attention output, pitch 132 to dodge bank conflicts)
//   ks    : 4*49*32 = 6272  [h][m][d]
//   vs    : 4*49*32 = 6272
//   ps    : 4*49*49 = 9604  softmax probs [h][n][m]
#define OFF_XS 0
#define OFF_KS 6468
#define OFF_VS 12740
#define OFF_PS 19012
#define SMEM_FLOATS (OFF_PS + HEADS*NWIN*NWIN)   // 28616
#define SMEM_BYTES  (SMEM_FLOATS * 4)            // 114464

__global__ __launch_bounds__(256, 2)
void winattn_kernel(const float* __restrict__ x,
                    const float* __restrict__ q_global,
                    const float* __restrict__ tbl,       // [169,4]
                    const float* __restrict__ W_kv,      // [128,256]
                    const float* __restrict__ b_kv,      // [256]
                    const float* __restrict__ W_proj,    // [128,128]
                    const float* __restrict__ b_proj,    // [128]
                    const int*   __restrict__ rel_index, // [49,49]
                    float* __restrict__ out)             // [4096,49,128]
{
    extern __shared__ float smem[];
    float* xs = smem + OFF_XS;   // phase 1-2: x tile (row pitch 128). phase 3b-4: o (row pitch 132)
    float* ks = smem + OFF_KS;
    float* vs = smem + OFF_VS;
    float* ps = smem + OFF_PS;

    const int b = blockIdx.x;
    const int t = threadIdx.x;

    // ---------------- phase 1: load x tile [49][128], contiguous ----------------
    {
        const float4* src = (const float4*)(x + (size_t)b * (NWIN * DIMC));
        float4* dst = (float4*)xs;
        #pragma unroll 2
        for (int i = t; i < NWIN * DIMC / 4; i += 256) dst[i] = src[i];
    }
    __syncthreads();

    // ---------------- phase 2: kv GEMM — thread t owns output column t ----------
    // kv[n, t], t = which*128 + h*32 + d  (which: 0=k, 1=v)
    {
        float acc[NWIN];
        const float bk = __ldg(&b_kv[t]);
        #pragma unroll
        for (int n = 0; n < NWIN; n++) acc[n] = bk;

        #pragma unroll 4
        for (int d0 = 0; d0 < DIMC; d0 += 4) {
            const float w0 = __ldg(&W_kv[(d0 + 0) * 256 + t]);
            const float w1 = __ldg(&W_kv[(d0 + 1) * 256 + t]);
            const float w2 = __ldg(&W_kv[(d0 + 2) * 256 + t]);
            const float w3 = __ldg(&W_kv[(d0 + 3) * 256 + t]);
            const float4* xv4 = (const float4*)xs + (d0 >> 2);
            #pragma unroll
            for (int n = 0; n < NWIN; n++) {
                float4 xv = xv4[n * 32];           // broadcast LDS.128
                acc[n] = fmaf(xv.x, w0, acc[n]);
                acc[n] = fmaf(xv.y, w1, acc[n]);
                acc[n] = fmaf(xv.z, w2, acc[n]);
                acc[n] = fmaf(xv.w, w3, acc[n]);
            }
        }
        float* dst = (t < 128) ? ks : vs;
        const int h = (t & 127) >> 5;
        const int d = t & 31;
        #pragma unroll
        for (int n = 0; n < NWIN; n++) dst[h * (NWIN * HD) + n * HD + d] = acc[n];
    }
    __syncthreads();

    // ---------------- phase 3a: scores + softmax, one (h,n) row per thread ------
    if (t < HEADS * NWIN) {
        const int h = t / NWIN;
        const int n = t % NWIN;

        float4 q[8];
        const float4* qg = (const float4*)(q_global
                            + ((size_t)(b >> 6) * HEADS + h) * (NWIN * HD) + n * HD);
        #pragma unroll
        for (int j = 0; j < 8; j++) {
            q[j] = __ldg(&qg[j]);
            q[j].x *= SCALE; q[j].y *= SCALE; q[j].z *= SCALE; q[j].w *= SCALE;
        }

        float s[NWIN];
        float mx = -1e30f;
        const int* ridx = rel_index + n * NWIN;
        #pragma unroll 7
        for (int m = 0; m < NWIN; m++) {
            const float4* kk = (const float4*)(ks + h * (NWIN * HD) + m * HD);
            float dot = 0.f;
            #pragma unroll
            for (int j = 0; j < 8; j++) {
                float4 kv = kk[j];
                dot = fmaf(q[j].x, kv.x, dot);
                dot = fmaf(q[j].y, kv.y, dot);
                dot = fmaf(q[j].z, kv.z, dot);
                dot = fmaf(q[j].w, kv.w, dot);
            }
            dot += __ldg(&tbl[__ldg(&ridx[m]) * HEADS + h]);
            s[m] = dot;
            mx = fmaxf(mx, dot);
        }
        float sum = 0.f;
        #pragma unroll
        for (int m = 0; m < NWIN; m++) { s[m] = __expf(s[m] - mx); sum += s[m]; }
        const float inv = 1.f / sum;
        float* prow = ps + (h * NWIN + n) * NWIN;
        #pragma unroll
        for (int m = 0; m < NWIN; m++) prow[m] = s[m] * inv;   // stride-49 across threads: conflict-free
    }
    __syncthreads();

    // ---------------- phase 3b: o[h][n][:] = p-row @ v, one (h,n) row per thread
    if (t < HEADS * NWIN) {
        const int h = t / NWIN;
        const int n = t % NWIN;
        float4 o[8];
        #pragma unroll
        for (int j = 0; j < 8; j++) o[j] = make_float4(0.f, 0.f, 0.f, 0.f);

        const float* prow = ps + (h * NWIN + n) * NWIN;
        #pragma unroll 7
        for (int m = 0; m < NWIN; m++) {
            const float p = prow[m];
            const float4* vv = (const float4*)(vs + h * (NWIN * HD) + m * HD);  // broadcast
            #pragma unroll
            for (int j = 0; j < 8; j++) {
                float4 v4 = vv[j];
                o[j].x = fmaf(p, v4.x, o[j].x);
                o[j].y = fmaf(p, v4.y, o[j].y);
                o[j].z = fmaf(p, v4.z, o[j].z);
                o[j].w = fmaf(p, v4.w, o[j].w);
            }
        }
        // write to os (= xs region, pitch 132 floats so STS.128 across n is conflict-free)
        float4* orow = (float4*)(xs + n * 132 + h * HD);
        #pragma unroll
        for (int j = 0; j < 8; j++) orow[j] = o[j];
    }
    __syncthreads();

    // ---------------- phase 4: proj GEMM — out[n][c] = o[n][:] @ W_proj[:,c] + b
    {
        const int c  = t & 127;
        const int n0 = (t < 128) ? 0 : 25;
        const int nr = (t < 128) ? 25 : 24;
        float acc[25];
        const float bp = __ldg(&b_proj[c]);
        #pragma unroll
        for (int i = 0; i < 25; i++) acc[i] = bp;

        #pragma unroll 4
        for (int d0 = 0; d0 < DIMC; d0 += 4) {
            const float w0 = __ldg(&W_proj[(d0 + 0) * DIMC + c]);
            const float w1 = __ldg(&W_proj[(d0 + 1) * DIMC + c]);
            const float w2 = __ldg(&W_proj[(d0 + 2) * DIMC + c]);
            const float w3 = __ldg(&W_proj[(d0 + 3) * DIMC + c]);
            #pragma unroll
            for (int i = 0; i < 25; i++) {
                if (i < nr) {
                    float4 xv = *(const float4*)(xs + (n0 + i) * 132 + d0);  // broadcast
                    acc[i] = fmaf(xv.x, w0, acc[i]);
                    acc[i] = fmaf(xv.y, w1, acc[i]);
                    acc[i] = fmaf(xv.z, w2, acc[i]);
                    acc[i] = fmaf(xv.w, w3, acc[i]);
                }
            }
        }
        float* obase = out + (size_t)b * (NWIN * DIMC) + c;
        #pragma unroll
        for (int i = 0; i < 25; i++) {
            if (i < nr) obase[(n0 + i) * DIMC] = acc[i];   // coalesced across c
        }
    }
}

extern "C" void kernel_launch(void* const* d_in, const int* in_sizes, int n_in,
                              void* d_out, int out_size)
{
    const float* x         = (const float*)d_in[0];
    const float* q_global  = (const float*)d_in[1];
    const float* tbl       = (const float*)d_in[2];
    const float* W_kv      = (const float*)d_in[3];
    const float* b_kv      = (const float*)d_in[4];
    const float* W_proj    = (const float*)d_in[5];
    const float* b_proj    = (const float*)d_in[6];
    const int*   rel_index = (const int*)d_in[7];
    float* out = (float*)d_out;

    cudaFuncSetAttribute(winattn_kernel,
                         cudaFuncAttributeMaxDynamicSharedMemorySize, SMEM_BYTES);

    winattn_kernel<<<4096, 256, SMEM_BYTES>>>(
        x, q_global, tbl, W_kv, b_kv, W_proj, b_proj, rel_index, out);
}